// round 7
// baseline (speedup 1.0000x reference)
#include <cuda_runtime.h>
#include <cuda_bf16.h>
#include <cstdint>

#define EPS       0.1f
#define NTHREADS  256
#define NWARPS    8
#define STAGES    3
#define TILE_B    2000               // bytes per TMA tile (multiple of 16)
#define NEG_LOG2E -1.4426950408889634f
#define LN2       0.6931471805599453f

typedef unsigned long long u64;

__device__ __forceinline__ float ex2f(float x) {
    float r; asm("ex2.approx.f32 %0, %1;" : "=f"(r) : "f"(x)); return r;
}
__device__ __forceinline__ float lg2f(float x) {
    float r; asm("lg2.approx.f32 %0, %1;" : "=f"(r) : "f"(x)); return r;
}
__device__ __forceinline__ uint32_t smem_u32(const void* p) {
    uint32_t a;
    asm("{ .reg .u64 t; cvta.to.shared.u64 t, %1; cvt.u32.u64 %0, t; }" : "=r"(a) : "l"(p));
    return a;
}
__device__ __forceinline__ void mbar_init(uint32_t mbar, uint32_t cnt) {
    asm volatile("mbarrier.init.shared.b64 [%0], %1;" :: "r"(mbar), "r"(cnt) : "memory");
}
__device__ __forceinline__ void fence_async() {
    asm volatile("fence.proxy.async.shared::cta;" ::: "memory");
}
__device__ __forceinline__ void mbar_expect_tx(uint32_t mbar, uint32_t bytes) {
    asm volatile("mbarrier.arrive.expect_tx.shared.b64 _, [%0], %1;"
                 :: "r"(mbar), "r"(bytes) : "memory");
}
__device__ __forceinline__ void bulk_g2s(uint32_t dst, const void* src,
                                         uint32_t bytes, uint32_t mbar) {
    asm volatile(
        "cp.async.bulk.shared::cluster.global.mbarrier::complete_tx::bytes "
        "[%0], [%1], %2, [%3];"
        :: "r"(dst), "l"(src), "r"(bytes), "r"(mbar) : "memory");
}
__device__ __forceinline__ void mbar_wait(uint32_t mbar, uint32_t parity) {
    uint32_t done;
    asm volatile(
        "{\n\t.reg .pred p;\n\t"
        "mbarrier.try_wait.parity.acquire.cta.shared::cta.b64 p, [%1], %2;\n\t"
        "selp.b32 %0, 1, 0, p;\n\t}"
        : "=r"(done) : "r"(mbar), "r"(parity) : "memory");
    if (!done) {
        asm volatile(
            "{\n\t.reg .pred P1;\n\t"
            "W_%=:\n\t"
            "mbarrier.try_wait.parity.acquire.cta.shared::cta.b64 P1, [%0], %1, 0x989680;\n\t"
            "@P1 bra.uni D_%=;\n\t"
            "bra.uni W_%=;\n\t"
            "D_%=:\n\t}"
            :: "r"(mbar), "r"(parity) : "memory");
    }
}

// Intrinsic-precision log-sigmoid for sparse correction terms + tails.
__device__ __forceinline__ float logsig_exact(float x) {
    float e = __expf(-fabsf(x));
    return fminf(x, 0.0f) - __logf(1.0f + e);
}

__global__ __launch_bounds__(NTHREADS) void ls_loss_kernel(
    const float* __restrict__ output,
    const int*   __restrict__ label,
    const int*   __restrict__ test_label,
    float*       __restrict__ out,
    int num_type, int L)
{
    // 8*3*2000 = 48000 B tiles + 192 B mbar + 512 B lab + 32 B warpsum = 48736 B
    __shared__ __align__(16) char tiles[NWARPS][STAGES][TILE_B];
    __shared__ __align__(8)  u64  mbar[NWARPS][STAGES];
    __shared__ int   lab[128];
    __shared__ float warpsum[NWARPS];

    const int b    = blockIdx.x;
    const int tid  = threadIdx.x;
    const int w    = tid >> 5;
    const int lane = tid & 31;
    const int twoL = 2 * L;

    if (tid < L)         lab[tid] = label[b * L + tid];
    else if (tid < twoL) lab[tid] = test_label[b * L + (tid - L)];

    const float  c0  = EPS / (float)num_type;
    const float* row = output + (size_t)b * (size_t)num_type;

    // ---- per-warp row partition (float4 granularity) ----
    const int nvec4  = num_type >> 2;
    const int pw     = (nvec4 + NWARPS - 1) / NWARPS;
    const int wbeg   = w * pw;
    const int wend   = min(wbeg + pw, nvec4);
    const int wbytes = (wend - wbeg) * 16;
    const int ntil   = (wbytes + TILE_B - 1) / TILE_B;   // tiles this warp owns
    const char* gsrc = (const char*)row + (size_t)wbeg * 16;

    const uint32_t mb = smem_u32(&mbar[w][0]);
    const uint32_t tb = smem_u32(&tiles[w][0][0]);

    // ---- per-warp pipeline init + prologue (no cross-warp sync needed) ----
    if (lane == 0) {
        #pragma unroll
        for (int s = 0; s < STAGES; s++) mbar_init(mb + 8 * s, 1);
        fence_async();
        #pragma unroll
        for (int s = 0; s < STAGES; s++) {
            if (s < ntil) {
                uint32_t sz = (uint32_t)min(TILE_B, wbytes - s * TILE_B);
                mbar_expect_tx(mb + 8 * s, sz);
                bulk_g2s(tb + s * TILE_B, gsrc + (size_t)s * TILE_B, sz, mb + 8 * s);
            }
        }
    }

    __syncthreads();   // lab[] visible to all (TMA already in flight)

    // ---- sparse resolution + early gather (latency hides under dense loop) ----
    float sp_w = 0.0f, sp_x = 0.0f;
    if (tid < twoL) {
        int raw = lab[tid];
        if (raw != 0) {
            bool canon = true;
            if (tid >= L) {
                for (int k = L; k < tid; k++)
                    if (lab[k] == raw) { canon = false; break; }
                if (canon) sp_w = 2.0f * (1.0f - EPS) - 2.0f * c0;
            } else {
                for (int k = 0; k < tid; k++)
                    if (lab[k] == raw) { canon = false; break; }
                if (canon)
                    for (int k = L; k < twoL; k++)
                        if (lab[k] == raw) { canon = false; break; }
                if (canon) sp_w = (1.0f - EPS) - c0;
            }
            if (sp_w != 0.0f) sp_x = __ldg(row + (raw - 1));
        }
    }

    // ---- dense mainloop: logsig(x) = -ln2 * lg2(1 + ex2(-x*log2e)) ----
    float L0 = 0.0f, L1 = 0.0f;

    int st = 0, parity = 0;
    for (int t = 0; t < ntil; t++) {
        mbar_wait(mb + 8 * st, parity);

        const int f4cnt = min(TILE_B, wbytes - t * TILE_B) >> 4;
        const float4* tp = (const float4*)&tiles[w][st][0];

        for (int i = lane; i < f4cnt; i += 32) {
            float4 v = tp[i];
            float e0 = ex2f(v.x * NEG_LOG2E);
            float e1 = ex2f(v.y * NEG_LOG2E);
            float e2 = ex2f(v.z * NEG_LOG2E);
            float e3 = ex2f(v.w * NEG_LOG2E);
            L0 += lg2f(1.0f + e0);
            L1 += lg2f(1.0f + e1);
            L0 += lg2f(1.0f + e2);
            L1 += lg2f(1.0f + e3);
        }

        // ALL lanes must be done reading this stage before lane 0 overwrites it.
        __syncwarp();

        const int nt = t + STAGES;
        if (lane == 0 && nt < ntil) {
            uint32_t sz = (uint32_t)min(TILE_B, wbytes - nt * TILE_B);
            mbar_expect_tx(mb + 8 * st, sz);
            bulk_g2s(tb + st * TILE_B, gsrc + (size_t)nt * TILE_B, sz, mb + 8 * st);
        }

        if (++st == STAGES) { st = 0; parity ^= 1; }
    }

    // scalar tail (num_type % 4; empty for this shape)
    float tail = 0.0f;
    for (int i = (nvec4 << 2) + tid; i < num_type; i += NTHREADS)
        tail += logsig_exact(row[i]);

    float acc = (-LN2 * c0) * (L0 + L1) + c0 * tail;
    acc += sp_w * logsig_exact(sp_x);   // weight 0 kills inactive lanes

    // ---- block reduction ----
    #pragma unroll
    for (int o = 16; o > 0; o >>= 1)
        acc += __shfl_down_sync(0xffffffffu, acc, o);
    if (lane == 0) warpsum[w] = acc;
    __syncthreads();

    if (tid < NWARPS) {
        float v = warpsum[tid];
        #pragma unroll
        for (int o = NWARPS / 2; o > 0; o >>= 1)
            v += __shfl_down_sync((1u << NWARPS) - 1u, v, o);
        if (tid == 0) out[b] = -v;
    }
}

extern "C" void kernel_launch(void* const* d_in, const int* in_sizes, int n_in,
                              void* d_out, int out_size)
{
    const float* output     = (const float*)d_in[0];
    const int*   label      = (const int*)d_in[1];
    const int*   test_label = (const int*)d_in[2];
    float*       out        = (float*)d_out;

    const int B        = out_size;               // 4096
    const int num_type = in_sizes[0] / B;        // 32000
    const int L        = in_sizes[1] / B;        // 50

    ls_loss_kernel<<<B, NTHREADS>>>(output, label, test_label, out, num_type, L);
}

// round 8
// speedup vs baseline: 1.8333x; 1.8333x over previous
#include <cuda_runtime.h>
#include <cuda_bf16.h>
#include <cstdint>

#define EPS       0.1f
#define CHUNKS    8          // blocks per row in the dense kernel
#define TA        256        // threads, dense kernel
#define TB        128        // threads, finalize kernel
#define NEG_LOG2E -1.4426950408889634f

// Degree-4 poly for ln(1+t), t in [0,1] (max abs err ~2e-4); B0 hoisted out.
#define PB0 2.012e-4f
#define PB1 0.9952132f
#define PB2 -0.4638212f
#define PB3 0.2162784f
#define PB4 -0.0548696f

typedef unsigned long long u64;

__device__ float g_partial[65536];   // up to 8192 rows * 8 chunks

__device__ __forceinline__ float ex2f(float x) {
    float r; asm("ex2.approx.f32 %0, %1;" : "=f"(r) : "f"(x)); return r;
}
__device__ __forceinline__ u64 pk2(float lo, float hi) {
    u64 r; asm("mov.b64 %0, {%1, %2};" : "=l"(r) : "f"(lo), "f"(hi)); return r;
}
__device__ __forceinline__ u64 fma2(u64 a, u64 b, u64 c) {
    u64 d; asm("fma.rn.f32x2 %0, %1, %2, %3;" : "=l"(d) : "l"(a), "l"(b), "l"(c)); return d;
}
__device__ __forceinline__ float2 up2(u64 v) {
    float lo, hi; asm("mov.b64 {%0, %1}, %2;" : "=f"(lo), "=f"(hi) : "l"(v));
    return make_float2(lo, hi);
}
// Intrinsic-precision log-sigmoid for sparse/tail terms.
__device__ __forceinline__ float logsig_exact(float x) {
    float e = __expf(-fabsf(x));
    return fminf(x, 0.0f) - __logf(1.0f + e);
}

// ---------------- Kernel A: dense partial sums, 8 blocks per row ----------------
// partial[blk] = sum over this chunk of [ min(x,0) - t*Q(t) ],  t = ex2(-|x|*log2e)
// (B0 constant excluded; folded in kernel B.)
__global__ __launch_bounds__(TA) void dense_partial_kernel(
    const float* __restrict__ mat, int num_type, int nvec4, int f4pc)
{
    const int blk   = blockIdx.x;
    const int row   = blk >> 3;          // CHUNKS == 8
    const int chunk = blk & (CHUNKS - 1);
    const int tid   = threadIdx.x;

    const float4* rowv = (const float4*)(mat + (size_t)row * (size_t)num_type);
    const int beg = chunk * f4pc;
    const int end = min(beg + f4pc, nvec4);

    const u64 B4p = pk2(PB4, PB4);
    const u64 B3p = pk2(PB3, PB3);
    const u64 B2p = pk2(PB2, PB2);
    const u64 B1p = pk2(PB1, PB1);

    float sm0 = 0.0f, sm1 = 0.0f;
    u64 G0 = 0ull, G1 = 0ull;

    #pragma unroll 4
    for (int i = beg + tid; i < end; i += TA) {
        float4 v = rowv[i];

        float t0 = ex2f(fabsf(v.x) * NEG_LOG2E);
        float t1 = ex2f(fabsf(v.y) * NEG_LOG2E);
        float t2 = ex2f(fabsf(v.z) * NEG_LOG2E);
        float t3 = ex2f(fabsf(v.w) * NEG_LOG2E);

        sm0 += fminf(v.x, 0.0f) + fminf(v.y, 0.0f);
        sm1 += fminf(v.z, 0.0f) + fminf(v.w, 0.0f);

        u64 ta = pk2(t0, t1);
        u64 tb = pk2(t2, t3);

        u64 p = fma2(ta, B4p, B3p);
        p     = fma2(ta, p,   B2p);
        p     = fma2(ta, p,   B1p);
        G0    = fma2(ta, p,   G0);

        u64 q = fma2(tb, B4p, B3p);
        q     = fma2(tb, q,   B2p);
        q     = fma2(tb, q,   B1p);
        G1    = fma2(tb, q,   G1);
    }

    float2 g0 = up2(G0), g1 = up2(G1);
    float  p  = (sm0 + sm1) - ((g0.x + g0.y) + (g1.x + g1.y));

    __shared__ float warpsum[TA / 32];
    #pragma unroll
    for (int o = 16; o > 0; o >>= 1)
        p += __shfl_down_sync(0xffffffffu, p, o);
    if ((tid & 31) == 0) warpsum[tid >> 5] = p;
    __syncthreads();
    if (tid < TA / 32) {
        float v = warpsum[tid];
        #pragma unroll
        for (int o = TA / 64; o > 0; o >>= 1)
            v += __shfl_down_sync(0xffu, v, o);
        if (tid == 0) g_partial[blk] = v;
    }
}

// ---------------- Kernel B: per-row finalize (sparse + combine) ----------------
__global__ __launch_bounds__(TB) void finalize_kernel(
    const float* __restrict__ mat,
    const int*   __restrict__ label,
    const int*   __restrict__ test_label,
    float*       __restrict__ out,
    int num_type, int L, int nvec4)
{
    const int b    = blockIdx.x;
    const int tid  = threadIdx.x;
    const int twoL = 2 * L;

    __shared__ int   lab[128];
    __shared__ float warpsum[TB / 32];

    if (tid < L)         lab[tid] = label[b * L + tid];
    else if (tid < twoL) lab[tid] = test_label[b * L + (tid - L)];
    __syncthreads();

    const float  c0  = EPS / (float)num_type;
    const float* row = mat + (size_t)b * (size_t)num_type;

    float acc = 0.0f;

    // dense partials (8 chunks) + hoisted B0 fold
    if (tid < CHUNKS) acc += c0 * g_partial[b * CHUNKS + tid];
    if (tid == 0)     acc -= c0 * (float)(nvec4 << 2) * PB0;

    // scalar tail beyond float4 region (empty when num_type % 4 == 0)
    for (int i = (nvec4 << 2) + tid; i < num_type; i += TB)
        acc += c0 * logsig_exact(row[i]);

    // sparse corrections with set semantics (dedup; test overwrites label)
    if (tid < twoL) {
        int raw = lab[tid];
        if (raw != 0) {
            bool canon = true;
            float w = 0.0f;
            if (tid >= L) {
                for (int k = L; k < tid; k++)
                    if (lab[k] == raw) { canon = false; break; }
                if (canon) w = 2.0f * (1.0f - EPS) - 2.0f * c0;
            } else {
                for (int k = 0; k < tid; k++)
                    if (lab[k] == raw) { canon = false; break; }
                if (canon)
                    for (int k = L; k < twoL; k++)
                        if (lab[k] == raw) { canon = false; break; }
                if (canon) w = (1.0f - EPS) - c0;
            }
            if (w != 0.0f) acc += w * logsig_exact(__ldg(row + (raw - 1)));
        }
    }

    // block reduction (128 threads)
    #pragma unroll
    for (int o = 16; o > 0; o >>= 1)
        acc += __shfl_down_sync(0xffffffffu, acc, o);
    if ((tid & 31) == 0) warpsum[tid >> 5] = acc;
    __syncthreads();
    if (tid < TB / 32) {
        float v = warpsum[tid];
        #pragma unroll
        for (int o = TB / 64; o > 0; o >>= 1)
            v += __shfl_down_sync(0xfu, v, o);
        if (tid == 0) out[b] = -v;
    }
}

extern "C" void kernel_launch(void* const* d_in, const int* in_sizes, int n_in,
                              void* d_out, int out_size)
{
    const float* output     = (const float*)d_in[0];
    const int*   label      = (const int*)d_in[1];
    const int*   test_label = (const int*)d_in[2];
    float*       out        = (float*)d_out;

    const int B        = out_size;               // 4096
    const int num_type = in_sizes[0] / B;        // 32000
    const int L        = in_sizes[1] / B;        // 50
    const int nvec4    = num_type >> 2;          // 8000
    const int f4pc     = (nvec4 + CHUNKS - 1) / CHUNKS;  // 1000

    dense_partial_kernel<<<B * CHUNKS, TA>>>(output, num_type, nvec4, f4pc);
    finalize_kernel<<<B, TB>>>(output, label, test_label, out, num_type, L, nvec4);
}

// round 10
// speedup vs baseline: 3.3010x; 1.8006x over previous
#include <cuda_runtime.h>
#include <cuda_bf16.h>
#include <cstdint>

#define EPS       0.1f
#define CHUNKS    16         // blocks per row in the dense kernel
#define TA        128        // threads, dense kernel
#define TB        128        // threads, finalize kernel
#define NEG_LOG2E -1.4426950408889634f

// Degree-4 poly for ln(1+t), t in [0,1] (max abs err ~2e-4); B0 hoisted out.
#define PB0 2.012e-4f
#define PB1 0.9952132f
#define PB2 -0.4638212f
#define PB3 0.2162784f
#define PB4 -0.0548696f

typedef unsigned long long u64;

__device__ float g_partial[65536];   // 4096 rows * 16 chunks

__device__ __forceinline__ float ex2f(float x) {
    float r; asm("ex2.approx.f32 %0, %1;" : "=f"(r) : "f"(x)); return r;
}
__device__ __forceinline__ u64 pk2(float lo, float hi) {
    u64 r; asm("mov.b64 %0, {%1, %2};" : "=l"(r) : "f"(lo), "f"(hi)); return r;
}
__device__ __forceinline__ u64 fma2(u64 a, u64 b, u64 c) {
    u64 d; asm("fma.rn.f32x2 %0, %1, %2, %3;" : "=l"(d) : "l"(a), "l"(b), "l"(c)); return d;
}
__device__ __forceinline__ float2 up2(u64 v) {
    float lo, hi; asm("mov.b64 {%0, %1}, %2;" : "=f"(lo), "=f"(hi) : "l"(v));
    return make_float2(lo, hi);
}
// Intrinsic-precision log-sigmoid for sparse/tail terms.
__device__ __forceinline__ float logsig_exact(float x) {
    float e = __expf(-fabsf(x));
    return fminf(x, 0.0f) - __logf(1.0f + e);
}

// ---------------- Kernel A: dense partial sums, 16 blocks per row ----------------
// partial[blk] = sum over chunk of [ min(x,0) - t*Q(t) ],  t = ex2(-|x|*log2e)
__global__ __launch_bounds__(TA) void dense_partial_kernel(
    const float* __restrict__ mat, int num_type, int nvec4, int f4pc)
{
    const int blk   = blockIdx.x;
    const int row   = blk >> 4;          // CHUNKS == 16
    const int chunk = blk & (CHUNKS - 1);
    const int tid   = threadIdx.x;

    const float4* rowv = (const float4*)(mat + (size_t)row * (size_t)num_type);
    const int beg = chunk * f4pc;
    const int end = min(beg + f4pc, nvec4);

    const u64 B4p = pk2(PB4, PB4);
    const u64 B3p = pk2(PB3, PB3);
    const u64 B2p = pk2(PB2, PB2);
    const u64 B1p = pk2(PB1, PB1);

    float sm0 = 0.0f, sm1 = 0.0f;
    u64 G0 = 0ull, G1 = 0ull;

    #pragma unroll 4
    for (int i = beg + tid; i < end; i += TA) {
        float4 v = rowv[i];

        float t0 = ex2f(fabsf(v.x) * NEG_LOG2E);
        float t1 = ex2f(fabsf(v.y) * NEG_LOG2E);
        float t2 = ex2f(fabsf(v.z) * NEG_LOG2E);
        float t3 = ex2f(fabsf(v.w) * NEG_LOG2E);

        sm0 += fminf(v.x, 0.0f) + fminf(v.y, 0.0f);
        sm1 += fminf(v.z, 0.0f) + fminf(v.w, 0.0f);

        u64 ta = pk2(t0, t1);
        u64 tb = pk2(t2, t3);

        u64 p = fma2(ta, B4p, B3p);
        p     = fma2(ta, p,   B2p);
        p     = fma2(ta, p,   B1p);
        G0    = fma2(ta, p,   G0);

        u64 q = fma2(tb, B4p, B3p);
        q     = fma2(tb, q,   B2p);
        q     = fma2(tb, q,   B1p);
        G1    = fma2(tb, q,   G1);
    }

    float2 g0 = up2(G0), g1 = up2(G1);
    float  p  = (sm0 + sm1) - ((g0.x + g0.y) + (g1.x + g1.y));

    __shared__ float warpsum[TA / 32];
    #pragma unroll
    for (int o = 16; o > 0; o >>= 1)
        p += __shfl_down_sync(0xffffffffu, p, o);
    if ((tid & 31) == 0) warpsum[tid >> 5] = p;
    __syncthreads();
    if (tid < TA / 32) {
        float v = warpsum[tid];
        #pragma unroll
        for (int o = TA / 64; o > 0; o >>= 1)
            v += __shfl_down_sync(0xfu, v, o);
        if (tid == 0) g_partial[blk] = v;
    }
}

// ---------------- Kernel B: per-row finalize (branchless dedup + combine) ----------------
__global__ __launch_bounds__(TB) void finalize_kernel(
    const float* __restrict__ mat,
    const int*   __restrict__ label,
    const int*   __restrict__ test_label,
    float*       __restrict__ out,
    int num_type, int L, int nvec4)
{
    const int b    = blockIdx.x;
    const int tid  = threadIdx.x;
    const int twoL = 2 * L;

    __shared__ int   lab[128];
    __shared__ float warpsum[TB / 32];

    if (tid < L)         lab[tid] = label[b * L + tid];
    else if (tid < twoL) lab[tid] = test_label[b * L + (tid - L)];
    __syncthreads();

    const float  c0  = EPS / (float)num_type;
    const float* row = mat + (size_t)b * (size_t)num_type;

    float acc = 0.0f;

    // dense partials (16 chunks) + hoisted B0 fold
    if (tid < CHUNKS) acc += c0 * g_partial[b * CHUNKS + tid];
    if (tid == 0)     acc -= c0 * (float)(nvec4 << 2) * PB0;

    // scalar tail beyond float4 region (empty when num_type % 4 == 0)
    for (int i = (nvec4 << 2) + tid; i < num_type; i += TB)
        acc += c0 * logsig_exact(row[i]);

    // ---- sparse corrections: BRANCHLESS dedup (no data-dependent breaks) ----
    // Entry tid (< twoL) is canonical iff:
    //   test entry  (tid>=L): no earlier test entry equals raw
    //   label entry (tid<L) : no earlier label entry equals raw AND
    //                         no test entry equals raw (test overwrites label)
    if (tid < twoL) {
        const int raw = lab[tid];
        int dup = (raw == 0);            // padding counts as non-canonical
        if (tid >= L) {
            #pragma unroll 5
            for (int k = L; k < twoL; k++)
                dup |= (k < tid) & (lab[k] == raw);
        } else {
            #pragma unroll 5
            for (int k = 0; k < L; k++)
                dup |= (k < tid) & (lab[k] == raw);
            #pragma unroll 5
            for (int k = L; k < twoL; k++)
                dup |= (lab[k] == raw);
        }
        const float w = dup ? 0.0f
                            : ((tid >= L) ? (2.0f * (1.0f - EPS) - 2.0f * c0)
                                          : ((1.0f - EPS) - c0));
        // index clamped so the load is always safe; w==0 kills the term
        const int j = (raw > 0) ? (raw - 1) : 0;
        acc += w * logsig_exact(__ldg(row + j));
    }

    // block reduction (128 threads)
    #pragma unroll
    for (int o = 16; o > 0; o >>= 1)
        acc += __shfl_down_sync(0xffffffffu, acc, o);
    if ((tid & 31) == 0) warpsum[tid >> 5] = acc;
    __syncthreads();
    if (tid < TB / 32) {
        float v = warpsum[tid];
        #pragma unroll
        for (int o = TB / 64; o > 0; o >>= 1)
            v += __shfl_down_sync(0xfu, v, o);
        if (tid == 0) out[b] = -v;
    }
}

extern "C" void kernel_launch(void* const* d_in, const int* in_sizes, int n_in,
                              void* d_out, int out_size)
{
    const float* output     = (const float*)d_in[0];
    const int*   label      = (const int*)d_in[1];
    const int*   test_label = (const int*)d_in[2];
    float*       out        = (float*)d_out;

    const int B        = out_size;               // 4096
    const int num_type = in_sizes[0] / B;        // 32000
    const int L        = in_sizes[1] / B;        // 50
    const int nvec4    = num_type >> 2;          // 8000
    const int f4pc     = (nvec4 + CHUNKS - 1) / CHUNKS;  // 500

    dense_partial_kernel<<<B * CHUNKS, TA>>>(output, num_type, nvec4, f4pc);
    finalize_kernel<<<B, TB>>>(output, label, test_label, out, num_type, L, nvec4);
}